// round 7
// baseline (speedup 1.0000x reference)
#include <cuda_runtime.h>
#include <math.h>

#define IMG    64
#define NSLICE 16
#define NCOIL  4
#define NSING  4
#define NECHO  3
#define NRO    32
#define NPT    96
#define NEC    (NECHO * NCOIL)   // 12
#define NPIX   (IMG * IMG)       // 4096

typedef unsigned long long u64;

// ---- packed f32x2 helpers ---------------------------------------------------
__device__ __forceinline__ u64 pack2(float lo, float hi) {
    u64 r;
    asm("mov.b64 %0, {%1, %2};" : "=l"(r)
        : "r"(__float_as_uint(lo)), "r"(__float_as_uint(hi)));
    return r;
}
__device__ __forceinline__ u64 dup2(float v) { return pack2(v, v); }
__device__ __forceinline__ void fma2(u64& d, u64 a, u64 b) {
    asm("fma.rn.f32x2 %0, %1, %2, %3;" : "=l"(d) : "l"(a), "l"(b), "l"(d));
}
__device__ __forceinline__ float2 unpack2(u64 v) {
    unsigned lo, hi;
    asm("mov.b64 {%0, %1}, %2;" : "=r"(lo), "=r"(hi) : "l"(v));
    return make_float2(__uint_as_float(lo), __uint_as_float(hi));
}

// scf[kz][c][j=n*3+e][pix]  (25 MB)
__device__ float2 g_scf[NSLICE * NCOIL * (NSING * NECHO) * NPIX];
// phase tables [r][x][p]
__device__ float2 g_exp_[NRO * IMG * NPT];   // exp(-i*w0*(x-32)) = (re, im)
__device__ float2 g_exr_[NRO * IMG * NPT];   // rotated:            (-im, re)
__device__ float2 g_ey_[NRO * IMG * NPT];    // exp(-i*w1*(y-32))

// ---------------------------------------------------------------------------
// Stage A: z-DFT (all 16 kz) of sign(z)*singulars*smap, per (pix, c, n).
// ---------------------------------------------------------------------------
__global__ __launch_bounds__(256, 2)
void stageA_kernel(const float* __restrict__ singulars,   // [64,64,16,4,3,2]
                   const float* __restrict__ smap)        // [4,64,64,16,2]
{
    const int pix = blockIdx.x * 256 + threadIdx.x;
    const int cn  = blockIdx.y;
    const int c   = cn >> 2;
    const int n   = cn & 3;
    const int x   = pix & (IMG - 1);
    const int y   = pix >> 6;

    __shared__ float2 W[NSLICE][NSLICE];
    {
        int kz = threadIdx.x >> 4, z = threadIdx.x & 15;
        float ang = -(2.0f * (float)M_PI / (float)NSLICE) * (float)(kz * z);
        float s, co; sincosf(ang, &s, &co);
        float sgn = (z & 1) ? -1.0f : 1.0f;
        W[kz][z] = make_float2(co * sgn, s * sgn);
    }
    __syncthreads();

    const float* vbase = singulars + ((size_t)(x * IMG + y) * NSLICE) * (NSING * NECHO * 2) + n * 6;
    const float* sbase = smap + ((size_t)(c * NPIX + x * IMG + y) * NSLICE) * 2;

    float accr[NSLICE][NECHO];
    float acci[NSLICE][NECHO];
#pragma unroll
    for (int kz = 0; kz < NSLICE; ++kz)
#pragma unroll
        for (int e = 0; e < NECHO; ++e) { accr[kz][e] = 0.f; acci[kz][e] = 0.f; }

    for (int z = 0; z < NSLICE; ++z) {
        float2 sm = *(const float2*)(sbase + z * 2);
        const float* v = vbase + z * (NSING * NECHO * 2);
        float2 v0 = *(const float2*)(v + 0);
        float2 v1 = *(const float2*)(v + 2);
        float2 v2 = *(const float2*)(v + 4);

        float tr[3], ti[3];
        tr[0] = v0.x * sm.x - v0.y * sm.y;  ti[0] = v0.x * sm.y + v0.y * sm.x;
        tr[1] = v1.x * sm.x - v1.y * sm.y;  ti[1] = v1.x * sm.y + v1.y * sm.x;
        tr[2] = v2.x * sm.x - v2.y * sm.y;  ti[2] = v2.x * sm.y + v2.y * sm.x;

#pragma unroll
        for (int kz = 0; kz < NSLICE; ++kz) {
            float2 w = W[kz][z];
#pragma unroll
            for (int e = 0; e < NECHO; ++e) {
                accr[kz][e] = fmaf(tr[e], w.x, accr[kz][e]);
                accr[kz][e] = fmaf(-ti[e], w.y, accr[kz][e]);
                acci[kz][e] = fmaf(tr[e], w.y, acci[kz][e]);
                acci[kz][e] = fmaf(ti[e], w.x, acci[kz][e]);
            }
        }
    }

#pragma unroll
    for (int kz = 0; kz < NSLICE; ++kz)
#pragma unroll
        for (int e = 0; e < NECHO; ++e) {
            g_scf[((size_t)(kz * NCOIL + c) * (NSING * NECHO) + n * NECHO + e) * NPIX + pix]
                = make_float2(accr[kz][e], acci[kz][e]);
        }
}

// ---------------------------------------------------------------------------
// Phase tables, parallel over 4 x-segments of 16. grid 32, block 384.
// ---------------------------------------------------------------------------
__global__ __launch_bounds__(384)
void exgen_kernel(const float* __restrict__ ktraj)   // [1,32,96,2]
{
    const int r = blockIdx.x;
    const int p = threadIdx.x % NPT;
    const int g = threadIdx.x / NPT;       // 0..3, 16 steps each
    const float w0 = ktraj[(r * NPT + p) * 2 + 0];
    const float w1 = ktraj[(r * NPT + p) * 2 + 1];

    {
        float s, c; sincosf(w0, &s, &c);                      // step exp(-i*w0)
        float pr, pi; sincosf(w0 * (32.0f - g * 16.0f), &pi, &pr);
#pragma unroll 4
        for (int j = 0; j < 16; ++j) {
            int x = g * 16 + j;
            size_t idx = ((size_t)r * IMG + x) * NPT + p;
            g_exp_[idx] = make_float2(pr, pi);
            g_exr_[idx] = make_float2(-pi, pr);
            float t = pr;
            pr = fmaf(pr, c, pi * s);
            pi = fmaf(pi, c, -(t * s));
        }
    }
    {
        float s, c; sincosf(w1, &s, &c);
        float pr, pi; sincosf(w1 * (32.0f - g * 16.0f), &pi, &pr);
#pragma unroll 4
        for (int j = 0; j < 16; ++j) {
            int y = g * 16 + j;
            g_ey_[((size_t)r * IMG + y) * NPT + p] = make_float2(pr, pi);
            float t = pr;
            pr = fmaf(pr, c, pi * s);
            pi = fmaf(pi, c, -(t * s));
        }
    }
}

// ---------------------------------------------------------------------------
// NUFFT (stageB fused into loader): grid (32 r, 12 ec), block 256 = 8 warps.
// Lane l owns points {l, l+32, l+64}; warp w owns ys [8w, 8w+8).
// Image stored PRE-DUPLICATED in smem: sDx[x][y]=(re,re), sDy[x][y]=(im,im)
// -> warp-uniform broadcast LDS.128 yields FFMA2 dup-operands directly
//    (zero ALU packing in the mainloop).
// smem 90KB -> 2 blocks/SM.
// ---------------------------------------------------------------------------
#define TS    66    // padded y-stride (u64) for dup image arrays
#define XPH   16    // x per table phase

__global__ __launch_bounds__(256, 2)
void nufft_kernel(const float* __restrict__ ur_list,   // [1,32,4]
                  const int*   __restrict__ sbin,      // [32]
                  float2* __restrict__ out)            // [96,4,32,3] complex
{
    extern __shared__ unsigned char shraw[];
    u64* sDx = (u64*)shraw;            // [64][TS] dup(re)
    u64* sDy = sDx + IMG * TS;         // [64][TS] dup(im)
    u64* sEp = sDy + IMG * TS;         // [XPH][96]
    u64* sEr = sEp + XPH * NPT;        // [XPH][96]
    float2* sRed = (float2*)sEp;       // overlay after mainloop: [96][8]

    const int r    = blockIdx.x;
    const int ec   = blockIdx.y;
    const int tid  = threadIdx.x;
    const int lane = tid & 31;
    const int w    = tid >> 5;
    const int y0   = w * 8;
    const int e    = ec >> 2;
    const int c    = ec & 3;

    // ---- loader: fused stageB (Ur mix over n) + dup-store ----
    {
        const int kzr = sbin[r];
        const float u0 = ur_list[r * NSING + 0];
        const float u1 = ur_list[r * NSING + 1];
        const float u2 = ur_list[r * NSING + 2];
        const float u3 = ur_list[r * NSING + 3];
        const float2* base = g_scf
            + ((size_t)(kzr * NCOIL + c) * (NSING * NECHO) + e) * NPIX;

        for (int i = tid; i < NPIX; i += 256) {
            float2 s0 = base[i];
            float2 s1 = base[i + 3 * NPIX];
            float2 s2 = base[i + 6 * NPIX];
            float2 s3 = base[i + 9 * NPIX];
            float ar = fmaf(u0, s0.x, fmaf(u1, s1.x, fmaf(u2, s2.x, u3 * s3.x)));
            float ai = fmaf(u0, s0.y, fmaf(u1, s1.y, fmaf(u2, s2.y, u3 * s3.y)));
            int x = i & 63, y = i >> 6;
            sDx[x * TS + y] = dup2(ar);
            sDy[x * TS + y] = dup2(ai);
        }
    }

    const u64* gep = (const u64*)(g_exp_ + (size_t)r * IMG * NPT);
    const u64* ger = (const u64*)(g_exr_ + (size_t)r * IMG * NPT);

    u64 acc[3][8];
#pragma unroll
    for (int a = 0; a < 3; ++a)
#pragma unroll
        for (int b = 0; b < 8; ++b) acc[a][b] = 0ull;

    for (int xb = 0; xb < IMG; xb += XPH) {
        if (xb) __syncthreads();
        for (int i = tid; i < XPH * NPT; i += 256) {
            sEp[i] = gep[xb * NPT + i];
            sEr[i] = ger[xb * NPT + i];
        }
        __syncthreads();   // also covers the dup-image loader on xb==0

#pragma unroll 2
        for (int xl = 0; xl < XPH; ++xl) {
            const u64* pe = sEp + xl * NPT;
            const u64* pr = sEr + xl * NPT;
            u64 ep0 = pe[lane], ep1 = pe[lane + 32], ep2 = pe[lane + 64];
            u64 er0 = pr[lane], er1 = pr[lane + 32], er2 = pr[lane + 64];

            const int ib = (xb + xl) * TS + y0;
#pragma unroll
            for (int j = 0; j < 4; ++j) {
                ulonglong2 dx = *(const ulonglong2*)(sDx + ib + 2 * j);  // dup re: y=2j, 2j+1
                ulonglong2 dy = *(const ulonglong2*)(sDy + ib + 2 * j);  // dup im
                fma2(acc[0][2*j],   dx.x, ep0); fma2(acc[0][2*j],   dy.x, er0);
                fma2(acc[1][2*j],   dx.x, ep1); fma2(acc[1][2*j],   dy.x, er1);
                fma2(acc[2][2*j],   dx.x, ep2); fma2(acc[2][2*j],   dy.x, er2);
                fma2(acc[0][2*j+1], dx.y, ep0); fma2(acc[0][2*j+1], dy.y, er0);
                fma2(acc[1][2*j+1], dx.y, ep1); fma2(acc[1][2*j+1], dy.y, er1);
                fma2(acc[2][2*j+1], dx.y, ep2); fma2(acc[2][2*j+1], dy.y, er2);
            }
        }
    }

    __syncthreads();   // mainloop's last table reads done; overlay sRed on sEp

    // epilogue: contract with ey over this warp's 8 ys
    const float2* gey = g_ey_ + (size_t)r * IMG * NPT;
#pragma unroll
    for (int k = 0; k < 3; ++k) {
        const int p = lane + 32 * k;
        float orr = 0.f, oii = 0.f;
#pragma unroll
        for (int yy = 0; yy < 8; ++yy) {
            float2 t  = unpack2(acc[k][yy]);
            float2 ey = gey[(y0 + yy) * NPT + p];
            orr = fmaf(t.x,  ey.x, orr);
            orr = fmaf(-t.y, ey.y, orr);
            oii = fmaf(t.x,  ey.y, oii);
            oii = fmaf(t.y,  ey.x, oii);
        }
        sRed[p * 8 + w] = make_float2(orr, oii);
    }
    __syncthreads();

    if (tid < NPT) {
        float sr = 0.f, si = 0.f;
#pragma unroll
        for (int q = 0; q < 8; ++q) {
            float2 v = sRed[tid * 8 + q];
            sr += v.x; si += v.y;
        }
        out[((tid * NCOIL + c) * NRO + r) * NECHO + e] = make_float2(sr, si);
    }
}

// ---------------------------------------------------------------------------
extern "C" void kernel_launch(void* const* d_in, const int* in_sizes, int n_in,
                              void* d_out, int out_size)
{
    const float* singulars = (const float*)d_in[0];
    const float* smap      = (const float*)d_in[1];
    const float* ktraj     = (const float*)d_in[2];
    const float* ur_list   = (const float*)d_in[3];
    const int*   sbin      = (const int*)d_in[4];
    // d_in[5] = dc (unused by the forward reference)

    float2* out = (float2*)d_out;

    const int smemNufft = (2 * IMG * TS + 2 * XPH * NPT) * (int)sizeof(u64);  // 90KB
    cudaFuncSetAttribute(nufft_kernel, cudaFuncAttributeMaxDynamicSharedMemorySize, smemNufft);

    stageA_kernel<<<dim3(NPIX / 256, 16), 256>>>(singulars, smap);
    exgen_kernel<<<NRO, 384>>>(ktraj);
    nufft_kernel<<<dim3(NRO, NEC), 256, smemNufft>>>(ur_list, sbin, out);
}

// round 9
// speedup vs baseline: 1.5696x; 1.5696x over previous
#include <cuda_runtime.h>
#include <math.h>
#include <stdint.h>

#define IMG    64
#define NSLICE 16
#define NCOIL  4
#define NSING  4
#define NECHO  3
#define NRO    32
#define NPT    96
#define NEC    (NECHO * NCOIL)   // 12
#define NPIX   (IMG * IMG)       // 4096

// scf[kz][c][j=n*3+e][pix]  (25 MB)
__device__ float2 g_scf[NSLICE * NCOIL * (NSING * NECHO) * NPIX];
// phase tables [r][x][p]
__device__ float2 g_exp_[NRO * IMG * NPT];   // exp(-i*w0*(x-32)) = (re, im)
__device__ float2 g_ey_[NRO * IMG * NPT];    // exp(-i*w1*(y-32))

// ---------------------------------------------------------------------------
// helpers
// ---------------------------------------------------------------------------
__device__ __forceinline__ float tf32r(float f) {
    uint32_t u;
    asm("cvt.rn.tf32.f32 %0, %1;" : "=r"(u) : "f"(f));
    return __uint_as_float(u);
}

// mma.sync m16n8k8 tf32: D = A*B + D (fp32 accum)
__device__ __forceinline__ void mma_tf32(float* d, const uint32_t* a, const uint32_t* b) {
    asm volatile(
        "mma.sync.aligned.m16n8k8.row.col.f32.tf32.tf32.f32 "
        "{%0,%1,%2,%3}, {%4,%5,%6,%7}, {%8,%9}, {%0,%1,%2,%3};"
        : "+f"(d[0]), "+f"(d[1]), "+f"(d[2]), "+f"(d[3])
        : "r"(a[0]), "r"(a[1]), "r"(a[2]), "r"(a[3]), "r"(b[0]), "r"(b[1]));
}

// ---------------------------------------------------------------------------
// Stage A: z-DFT (all 16 kz) of sign(z)*singulars*smap, per (pix, c, n).
// ---------------------------------------------------------------------------
__global__ __launch_bounds__(256, 2)
void stageA_kernel(const float* __restrict__ singulars,   // [64,64,16,4,3,2]
                   const float* __restrict__ smap)        // [4,64,64,16,2]
{
    const int pix = blockIdx.x * 256 + threadIdx.x;
    const int cn  = blockIdx.y;
    const int c   = cn >> 2;
    const int n   = cn & 3;
    const int x   = pix & (IMG - 1);
    const int y   = pix >> 6;

    __shared__ float2 W[NSLICE][NSLICE];
    {
        int kz = threadIdx.x >> 4, z = threadIdx.x & 15;
        float ang = -(2.0f * (float)M_PI / (float)NSLICE) * (float)(kz * z);
        float s, co; sincosf(ang, &s, &co);
        float sgn = (z & 1) ? -1.0f : 1.0f;
        W[kz][z] = make_float2(co * sgn, s * sgn);
    }
    __syncthreads();

    const float* vbase = singulars + ((size_t)(x * IMG + y) * NSLICE) * (NSING * NECHO * 2) + n * 6;
    const float* sbase = smap + ((size_t)(c * NPIX + x * IMG + y) * NSLICE) * 2;

    float accr[NSLICE][NECHO];
    float acci[NSLICE][NECHO];
#pragma unroll
    for (int kz = 0; kz < NSLICE; ++kz)
#pragma unroll
        for (int e = 0; e < NECHO; ++e) { accr[kz][e] = 0.f; acci[kz][e] = 0.f; }

    for (int z = 0; z < NSLICE; ++z) {
        float2 sm = *(const float2*)(sbase + z * 2);
        const float* v = vbase + z * (NSING * NECHO * 2);
        float2 v0 = *(const float2*)(v + 0);
        float2 v1 = *(const float2*)(v + 2);
        float2 v2 = *(const float2*)(v + 4);

        float tr[3], ti[3];
        tr[0] = v0.x * sm.x - v0.y * sm.y;  ti[0] = v0.x * sm.y + v0.y * sm.x;
        tr[1] = v1.x * sm.x - v1.y * sm.y;  ti[1] = v1.x * sm.y + v1.y * sm.x;
        tr[2] = v2.x * sm.x - v2.y * sm.y;  ti[2] = v2.x * sm.y + v2.y * sm.x;

#pragma unroll
        for (int kz = 0; kz < NSLICE; ++kz) {
            float2 w = W[kz][z];
#pragma unroll
            for (int e = 0; e < NECHO; ++e) {
                accr[kz][e] = fmaf(tr[e], w.x, accr[kz][e]);
                accr[kz][e] = fmaf(-ti[e], w.y, accr[kz][e]);
                acci[kz][e] = fmaf(tr[e], w.y, acci[kz][e]);
                acci[kz][e] = fmaf(ti[e], w.x, acci[kz][e]);
            }
        }
    }

#pragma unroll
    for (int kz = 0; kz < NSLICE; ++kz)
#pragma unroll
        for (int e = 0; e < NECHO; ++e) {
            g_scf[((size_t)(kz * NCOIL + c) * (NSING * NECHO) + n * NECHO + e) * NPIX + pix]
                = make_float2(accr[kz][e], acci[kz][e]);
        }
}

// ---------------------------------------------------------------------------
// Phase tables, parallel over 4 x-segments of 16. grid 32, block 384.
// ---------------------------------------------------------------------------
__global__ __launch_bounds__(384)
void exgen_kernel(const float* __restrict__ ktraj)   // [1,32,96,2]
{
    const int r = blockIdx.x;
    const int p = threadIdx.x % NPT;
    const int g = threadIdx.x / NPT;       // 0..3, 16 steps each
    const float w0 = ktraj[(r * NPT + p) * 2 + 0];
    const float w1 = ktraj[(r * NPT + p) * 2 + 1];

    {
        float s, c; sincosf(w0, &s, &c);                      // step exp(-i*w0)
        float pr, pi; sincosf(w0 * (32.0f - g * 16.0f), &pi, &pr);
#pragma unroll 4
        for (int j = 0; j < 16; ++j) {
            int x = g * 16 + j;
            g_exp_[((size_t)r * IMG + x) * NPT + p] = make_float2(pr, pi);
            float t = pr;
            pr = fmaf(pr, c, pi * s);
            pi = fmaf(pi, c, -(t * s));
        }
    }
    {
        float s, c; sincosf(w1, &s, &c);
        float pr, pi; sincosf(w1 * (32.0f - g * 16.0f), &pi, &pr);
#pragma unroll 4
        for (int j = 0; j < 16; ++j) {
            int y = g * 16 + j;
            g_ey_[((size_t)r * IMG + y) * NPT + p] = make_float2(pr, pi);
            float t = pr;
            pr = fmaf(pr, c, pi * s);
            pi = fmaf(pi, c, -(t * s));
        }
    }
}

// ---------------------------------------------------------------------------
// NUFFT via warp-level mma.sync (tf32): per (r, ec) a real GEMM
//   C[96 x 128] = A[96 x 128] . B^T,  A = [ex.re | -ex.im],
//   B rows: [y]=[img.re | img.im], [64+y]=[img.im | -img.re]
// grid (32 r, 4 ecg), block 256 (8 warps: m-split 2 x n-split 4).
// Each warp: 3 m-tiles (m16) x 4 n-tiles (n8), K = 16 x k8.
// smem: A [96][132] + B [128][132] + partials; B overlaid with C for epilogue.
// ---------------------------------------------------------------------------
#define KS       132                  // float stride (== 4 mod 32: conflict-free frags)
#define A_FLOATS (96 * KS)
#define B_FLOATS (128 * KS)

__global__ __launch_bounds__(256, 1)
void nufft_mma_kernel(const float* __restrict__ ur_list,   // [1,32,4]
                      const int*   __restrict__ sbin,      // [32]
                      float2* __restrict__ out)            // [96,4,32,3]
{
    extern __shared__ float sh[];
    float*  sA   = sh;                       // [96][KS]
    float*  sB   = sh + A_FLOATS;            // [128][KS], overlaid with C (t1)
    float2* sPar = (float2*)(sh + A_FLOATS + B_FLOATS);   // [96][2]

    const int r    = blockIdx.x;
    const int ecg  = blockIdx.y;
    const int tid  = threadIdx.x;
    const int lane = tid & 31;
    const int w    = tid >> 5;
    const int g    = lane >> 2;     // 0..7
    const int tg   = lane & 3;      // 0..3
    const int mg   = w >> 2;        // 0..1  (m-rows 48*mg ..)
    const int ng   = w & 3;         // 0..3  (n-cols 32*ng ..)

    // ---- build A (tf32): A[p][x] = ex.re, A[p][64+x] = -ex.im ----
    {
        const float2* gexp = g_exp_ + (size_t)r * IMG * NPT;
        for (int i = tid; i < IMG * NPT; i += 256) {
            int x = i / NPT, p = i % NPT;
            float2 e = gexp[i];
            sA[p * KS + x]      = tf32r(e.x);
            sA[p * KS + 64 + x] = tf32r(-e.y);
        }
    }

    const int kzr = sbin[r];
    const float u0 = ur_list[r * NSING + 0];
    const float u1 = ur_list[r * NSING + 1];
    const float u2 = ur_list[r * NSING + 2];
    const float u3 = ur_list[r * NSING + 3];

    const float* Abase = sA + (mg * 48 + g) * KS + tg;
    const float* Bbase = sB + (ng * 32 + g) * KS + tg;
    const float2* gey  = g_ey_ + (size_t)r * IMG * NPT;

    for (int it = 0; it < 3; ++it) {
        const int ec = ecg * 3 + it;
        const int e  = ec >> 2;
        const int c  = ec & 3;

        __syncthreads();   // prior epilogue readers of sB done (and A build on it==0)

        // ---- build B for this ec (fused Ur mix) ----
        const float2* base = g_scf
            + ((size_t)(kzr * NCOIL + c) * (NSING * NECHO) + e) * NPIX;
        for (int i = tid; i < NPIX; i += 256) {
            float2 s0 = base[i];
            float2 s1 = base[i + 3 * NPIX];
            float2 s2 = base[i + 6 * NPIX];
            float2 s3 = base[i + 9 * NPIX];
            float ar = fmaf(u0, s0.x, fmaf(u1, s1.x, fmaf(u2, s2.x, u3 * s3.x)));
            float ai = fmaf(u0, s0.y, fmaf(u1, s1.y, fmaf(u2, s2.y, u3 * s3.y)));
            int x = i & 63, y = i >> 6;
            float tar = tf32r(ar), tai = tf32r(ai);
            sB[y * KS + x]             = tar;
            sB[y * KS + 64 + x]        = tai;
            sB[(64 + y) * KS + x]      = tai;
            sB[(64 + y) * KS + 64 + x] = tf32r(-ar);
        }
        __syncthreads();

        // ---- mma mainloop: K = 128 in 16 k8 steps ----
        float d[3][4][4];
#pragma unroll
        for (int mt = 0; mt < 3; ++mt)
#pragma unroll
            for (int nt = 0; nt < 4; ++nt)
#pragma unroll
                for (int q = 0; q < 4; ++q) d[mt][nt][q] = 0.f;

#pragma unroll
        for (int k0 = 0; k0 < 128; k0 += 8) {
            uint32_t a[3][4], b[4][2];
#pragma unroll
            for (int mt = 0; mt < 3; ++mt) {
                const float* ap = Abase + mt * 16 * KS + k0;
                a[mt][0] = __float_as_uint(ap[0]);
                a[mt][1] = __float_as_uint(ap[8 * KS]);
                a[mt][2] = __float_as_uint(ap[4]);
                a[mt][3] = __float_as_uint(ap[8 * KS + 4]);
            }
#pragma unroll
            for (int nt = 0; nt < 4; ++nt) {
                const float* bp = Bbase + nt * 8 * KS + k0;
                b[nt][0] = __float_as_uint(bp[0]);
                b[nt][1] = __float_as_uint(bp[4]);
            }
#pragma unroll
            for (int mt = 0; mt < 3; ++mt)
#pragma unroll
                for (int nt = 0; nt < 4; ++nt)
                    mma_tf32(d[mt][nt], a[mt], b[nt]);
        }

        __syncthreads();   // everyone done reading sB -> overlay C

        // ---- store C (t1) into sB overlay: t1[p][n], rows 0..95 ----
#pragma unroll
        for (int mt = 0; mt < 3; ++mt) {
#pragma unroll
            for (int nt = 0; nt < 4; ++nt) {
                int p = mg * 48 + mt * 16 + g;
                int n = ng * 32 + nt * 8 + 2 * tg;
                sB[p * KS + n]           = d[mt][nt][0];
                sB[p * KS + n + 1]       = d[mt][nt][1];
                sB[(p + 8) * KS + n]     = d[mt][nt][2];
                sB[(p + 8) * KS + n + 1] = d[mt][nt][3];
            }
        }
        __syncthreads();

        // ---- ey contraction: thread (p, h) handles y in [32h, 32h+32) ----
        if (tid < 192) {
            int p = tid % 96, h = tid / 96;
            float orr = 0.f, oii = 0.f;
            const float* rowp = sB + p * KS;
#pragma unroll 8
            for (int y = 32 * h; y < 32 * h + 32; ++y) {
                float tr = rowp[y];
                float ti = rowp[64 + y];
                float2 ey = gey[y * NPT + p];
                orr = fmaf(tr,  ey.x, orr);
                orr = fmaf(-ti, ey.y, orr);
                oii = fmaf(tr,  ey.y, oii);
                oii = fmaf(ti,  ey.x, oii);
            }
            sPar[p * 2 + h] = make_float2(orr, oii);
        }
        __syncthreads();

        if (tid < NPT) {
            float2 v0 = sPar[tid * 2 + 0];
            float2 v1 = sPar[tid * 2 + 1];
            out[((tid * NCOIL + c) * NRO + r) * NECHO + e]
                = make_float2(v0.x + v1.x, v0.y + v1.y);
        }
    }
}

// ---------------------------------------------------------------------------
extern "C" void kernel_launch(void* const* d_in, const int* in_sizes, int n_in,
                              void* d_out, int out_size)
{
    const float* singulars = (const float*)d_in[0];
    const float* smap      = (const float*)d_in[1];
    const float* ktraj     = (const float*)d_in[2];
    const float* ur_list   = (const float*)d_in[3];
    const int*   sbin      = (const int*)d_in[4];
    // d_in[5] = dc (unused by the forward reference)

    float2* out = (float2*)d_out;

    const int smemNufft = (A_FLOATS + B_FLOATS) * (int)sizeof(float)
                        + 96 * 2 * (int)sizeof(float2);    // ~117KB
    cudaFuncSetAttribute(nufft_mma_kernel,
                         cudaFuncAttributeMaxDynamicSharedMemorySize, smemNufft);

    stageA_kernel<<<dim3(NPIX / 256, 16), 256>>>(singulars, smap);
    exgen_kernel<<<NRO, 384>>>(ktraj);
    nufft_mma_kernel<<<dim3(NRO, 4), 256, smemNufft>>>(ur_list, sbin, out);
}